// round 1
// baseline (speedup 1.0000x reference)
#include <cuda_runtime.h>

#define NQ      10
#define LAYERS  4
#define DIM     784
#define NOUT    10
#define NGATES  (LAYERS * NQ)

// Precomputed gate coefficients: for each (layer, qubit): {ar, ai, br, bi}
// Rot matrix = [[a, b], [-conj(b), conj(a)]],
//   a = exp(-i(phi+omega)/2) * cos(theta/2)
//   b = -exp(+i(phi-omega)/2) * sin(theta/2)
__device__ float g_gates[NGATES * 4];

__global__ void precompute_gates_kernel(const float* __restrict__ qw) {
    int i = threadIdx.x;
    if (i < NGATES) {
        float phi = qw[i * 3 + 0];
        float th  = qw[i * 3 + 1];
        float om  = qw[i * 3 + 2];
        float c, s, cp, sp, cm, sm;
        __sincosf(th * 0.5f, &s, &c);
        // use precise sincos for the phases too (accuracy headroom)
        sincosf((phi + om) * 0.5f, &sp, &cp);
        sincosf((phi - om) * 0.5f, &sm, &cm);
        s = sinf(th * 0.5f);
        c = cosf(th * 0.5f);
        g_gates[i * 4 + 0] =  cp * c;   // ar
        g_gates[i * 4 + 1] = -sp * c;   // ai
        g_gates[i * 4 + 2] = -cm * s;   // br
        g_gates[i * 4 + 3] = -sm * s;   // bi
    }
}

__global__ __launch_bounds__(256)
void qnet_kernel(const float* __restrict__ x,
                 const float* __restrict__ Wp,
                 const float* __restrict__ bp,
                 const float* __restrict__ Wo,
                 const float* __restrict__ bo,
                 float* __restrict__ out,
                 int batch) {
    __shared__ float sg[NGATES * 4];
    for (int i = threadIdx.x; i < NGATES * 4; i += blockDim.x)
        sg[i] = g_gates[i];
    __syncthreads();

    const int warp = (int)((blockIdx.x * blockDim.x + threadIdx.x) >> 5);
    const int lane = threadIdx.x & 31;
    if (warp >= batch) return;

    // ---------------- input projection: h = tanh(x @ Wp^T + bp) -------------
    const float* xr = x + (size_t)warp * DIM;
    float acc[NQ];
#pragma unroll
    for (int q = 0; q < NQ; q++) acc[q] = 0.f;
    for (int d = lane; d < DIM; d += 32) {
        float xv = __ldg(xr + d);
#pragma unroll
        for (int q = 0; q < NQ; q++)
            acc[q] = fmaf(xv, __ldg(Wp + q * DIM + d), acc[q]);
    }
#pragma unroll
    for (int m = 16; m >= 1; m >>= 1) {
#pragma unroll
        for (int q = 0; q < NQ; q++)
            acc[q] += __shfl_xor_sync(0xffffffffu, acc[q], m);
    }
    float cq[NQ], sq[NQ];
#pragma unroll
    for (int q = 0; q < NQ; q++) {
        float h = tanhf(acc[q] + bp[q]);
        sincosf(0.5f * h, &sq[q], &cq[q]);
    }

    // ---------------- embedding: real product state --------------------------
    // amplitude index n: bits [4:0] = local r (qubits 0..4), bits [9:5] = lane
    // (qubits 5..9).  amp[n] = prod_q (bit_q(n) ? sin : cos)
    float lp = 1.f;
#pragma unroll
    for (int k = 0; k < 5; k++)
        lp *= ((lane >> k) & 1) ? sq[5 + k] : cq[5 + k];

    float re[32], im[32];
#pragma unroll
    for (int r = 0; r < 32; r++) {
        float v = lp;
#pragma unroll
        for (int k = 0; k < 5; k++)
            v *= ((r >> k) & 1) ? sq[k] : cq[k];
        re[r] = v;
        im[r] = 0.f;
    }

    // ---------------- entangling layers --------------------------------------
#pragma unroll
    for (int l = 0; l < LAYERS; l++) {
        // --- Rot gates on every qubit ---
#pragma unroll
        for (int q = 0; q < NQ; q++) {
            const float ar = sg[(l * NQ + q) * 4 + 0];
            const float ai = sg[(l * NQ + q) * 4 + 1];
            const float br = sg[(l * NQ + q) * 4 + 2];
            const float bi = sg[(l * NQ + q) * 4 + 3];
            // u00=(ar,ai)  u01=(br,bi)  u10=(-br,bi)  u11=(ar,-ai)
            if (q < 5) {
                const int m = 1 << q;
#pragma unroll
                for (int r = 0; r < 32; r++) {
                    if (r & m) continue;
                    const int r1 = r | m;
                    const float are = re[r],  aim = im[r];
                    const float bre = re[r1], bim = im[r1];
                    re[r]  =  ar * are - ai * aim + br * bre - bi * bim;
                    im[r]  =  ar * aim + ai * are + br * bim + bi * bre;
                    re[r1] = -br * are - bi * aim + ar * bre + ai * bim;
                    im[r1] = -br * aim + bi * are + ar * bim - ai * bre;
                }
            } else {
                const int msk = 1 << (q - 5);
                const bool hi = (lane >> (q - 5)) & 1;
                // my coeff cm = hi ? u11 : u00 ; other coeff co = hi ? u10 : u01
                const float cmr = ar;
                const float cmi = hi ? -ai : ai;
                const float cor = hi ? -br : br;
                const float coi = bi;
#pragma unroll
                for (int r = 0; r < 32; r++) {
                    const float ore = __shfl_xor_sync(0xffffffffu, re[r], msk);
                    const float oim = __shfl_xor_sync(0xffffffffu, im[r], msk);
                    const float mre = re[r], mim = im[r];
                    re[r] = cmr * mre - cmi * mim + cor * ore - coi * oim;
                    im[r] = cmr * mim + cmi * mre + cor * oim + coi * ore;
                }
            }
        }

        // --- CNOT ring: (q -> q+1) for q=0..8, then (9 -> 0) ---
        // q=0..3: control & target both local
#pragma unroll
        for (int q = 0; q < 4; q++) {
            const int cm_ = 1 << q, tm = 1 << (q + 1);
#pragma unroll
            for (int r = 0; r < 32; r++) {
                if ((r & cm_) && !(r & tm)) {
                    const int r1 = r | tm;
                    float t;
                    t = re[r]; re[r] = re[r1]; re[r1] = t;
                    t = im[r]; im[r] = im[r1]; im[r1] = t;
                }
            }
        }
        // q=4: control = local bit4, target = lane bit0 (qubit 5)
#pragma unroll
        for (int r = 16; r < 32; r++) {
            re[r] = __shfl_xor_sync(0xffffffffu, re[r], 1);
            im[r] = __shfl_xor_sync(0xffffffffu, im[r], 1);
        }
        // q=5..8: control = lane bit (q-5), target = lane bit (q-4)
#pragma unroll
        for (int q = 5; q < 9; q++) {
            const int tmask = 1 << (q - 4);
            const bool ctl = (lane >> (q - 5)) & 1;
#pragma unroll
            for (int r = 0; r < 32; r++) {
                const float ore = __shfl_xor_sync(0xffffffffu, re[r], tmask);
                const float oim = __shfl_xor_sync(0xffffffffu, im[r], tmask);
                if (ctl) { re[r] = ore; im[r] = oim; }
            }
        }
        // q=9: control = lane bit4, target = local bit0
        if (lane & 16) {
#pragma unroll
            for (int r = 0; r < 32; r += 2) {
                float t;
                t = re[r]; re[r] = re[r + 1]; re[r + 1] = t;
                t = im[r]; im[r] = im[r + 1]; im[r + 1] = t;
            }
        }
    }

    // ---------------- Z expectations ------------------------------------------
    float tot = 0.f;
    float zlo[5];
#pragma unroll
    for (int k = 0; k < 5; k++) zlo[k] = 0.f;
#pragma unroll
    for (int r = 0; r < 32; r++) {
        const float pr = re[r] * re[r] + im[r] * im[r];
        tot += pr;
#pragma unroll
        for (int k = 0; k < 5; k++)
            zlo[k] += ((r >> k) & 1) ? -pr : pr;
    }
    float z[NQ];
#pragma unroll
    for (int k = 0; k < 5; k++) z[k] = zlo[k];
#pragma unroll
    for (int k = 0; k < 5; k++)
        z[5 + k] = ((lane >> k) & 1) ? -tot : tot;
#pragma unroll
    for (int m = 16; m >= 1; m >>= 1) {
#pragma unroll
        for (int q = 0; q < NQ; q++)
            z[q] += __shfl_xor_sync(0xffffffffu, z[q], m);
    }

    // ---------------- output projection ---------------------------------------
    if (lane < NOUT) {
        float o = bo[lane];
#pragma unroll
        for (int q = 0; q < NQ; q++)
            o = fmaf(z[q], Wo[lane * NQ + q], o);
        out[(size_t)warp * NOUT + lane] = o;
    }
}

extern "C" void kernel_launch(void* const* d_in, const int* in_sizes, int n_in,
                              void* d_out, int out_size) {
    const float* x  = (const float*)d_in[0];   // (B, 784)
    const float* Wp = (const float*)d_in[1];   // (10, 784)
    const float* bp = (const float*)d_in[2];   // (10,)
    const float* qw = (const float*)d_in[3];   // (4, 10, 3)
    const float* Wo = (const float*)d_in[4];   // (10, 10)
    const float* bo = (const float*)d_in[5];   // (10,)
    float* out = (float*)d_out;                // (B, 10)

    const int batch = in_sizes[0] / DIM;

    precompute_gates_kernel<<<1, 64>>>(qw);

    const int warps_per_block = 8;             // 256 threads
    const int blocks = (batch + warps_per_block - 1) / warps_per_block;
    qnet_kernel<<<blocks, warps_per_block * 32>>>(x, Wp, bp, Wo, bo, out, batch);
}

// round 4
// speedup vs baseline: 1.7225x; 1.7225x over previous
#include <cuda_runtime.h>

typedef unsigned long long ull;

#define NQ 10
#define LAYERS 4
#define DIM 784
#define DIM4 (DIM / 4)
#define NOUT 10
#define NGATES (LAYERS * NQ)

// Precomputed gate coefficients: for each (layer, qubit): {ar, ai, br, bi}
// Rot = [[a, b], [-conj(b), conj(a)]],
//   a = exp(-i(phi+omega)/2) cos(th/2),  b = -exp(+i(phi-omega)/2) sin(th/2)
__device__ float g_gates[NGATES * 4];

__global__ void precompute_gates_kernel(const float* __restrict__ qw) {
    int i = threadIdx.x;
    if (i < NGATES) {
        float phi = qw[i * 3 + 0], th = qw[i * 3 + 1], om = qw[i * 3 + 2];
        float s = sinf(th * 0.5f), c = cosf(th * 0.5f);
        float sp, cp, sm, cm;
        sincosf((phi + om) * 0.5f, &sp, &cp);
        sincosf((phi - om) * 0.5f, &sm, &cm);
        g_gates[i * 4 + 0] =  cp * c;
        g_gates[i * 4 + 1] = -sp * c;
        g_gates[i * 4 + 2] = -cm * s;
        g_gates[i * 4 + 3] = -sm * s;
    }
}

// ---------------- f32x2 helpers (FFMA2 only reachable via PTX) --------------
__device__ __forceinline__ ull pk(float a, float b) {
    ull r; asm("mov.b64 %0,{%1,%2};" : "=l"(r) : "f"(a), "f"(b)); return r;
}
__device__ __forceinline__ void upk(ull v, float& a, float& b) {
    asm("mov.b64 {%0,%1},%2;" : "=f"(a), "=f"(b) : "l"(v));
}
__device__ __forceinline__ ull swp(ull v) { float a, b; upk(v, a, b); return pk(b, a); }
__device__ __forceinline__ ull fma2(ull a, ull b, ull c) {
    ull d; asm("fma.rn.f32x2 %0,%1,%2,%3;" : "=l"(d) : "l"(a), "l"(b), "l"(c)); return d;
}
__device__ __forceinline__ ull mul2(ull a, ull b) {
    ull d; asm("mul.rn.f32x2 %0,%1,%2;" : "=l"(d) : "l"(a), "l"(b)); return d;
}

// ---------------- generalized Rot gate --------------------------------------
// Physical index: bits[3:0]+bit4 = local (pair idx p = bits[3:0], half = bit4),
// bits[9:5] = lane. Gate pairs sites along phys XOR mask V; logical-bit-q value
// at a site is parity(S & phys). Site formula (h = logical bit):
//   new = h==0 ?  a*m + b*o  :  conj(a)*m - conj(b)*o
// folded into sign-baked coefficient pairs (per half of the f32x2 pack).
template<unsigned V, unsigned S>
__device__ __forceinline__ void gate(ull* reP, ull* imP, const float* g, unsigned lane) {
    const float ar = g[0], ai = g[1], br = g[2], bi = g[3];
    constexpr unsigned VLANE = V >> 5;
    constexpr unsigned VL15  = V & 15u;
    constexpr bool     V4    = ((V >> 4) & 1u) != 0;
    constexpr unsigned SLANE = S >> 5;
    constexpr unsigned SL15  = S & 15u;
    constexpr bool     S4    = ((S >> 4) & 1u) != 0;

    unsigned sgn = SLANE ? ((unsigned)(__popc(lane & SLANE) & 1) << 31) : 0u;
    float cmi0  = __uint_as_float(__float_as_uint(ai) ^ sgn);
    float cor0  = __uint_as_float(__float_as_uint(br) ^ sgn);
    float cmi0h = S4 ? -cmi0 : cmi0;
    float cor0h = S4 ? -cor0 : cor0;
    ull arP   = pk(ar, ar);
    ull biP   = pk(bi, bi);
    ull nbiP  = pk(-bi, -bi);
    ull cmiP0 = pk(cmi0, cmi0h), cmiP1 = pk(-cmi0, -cmi0h);
    ull corP0 = pk(cor0, cor0h), corP1 = pk(-cor0, -cor0h);

    // re_new = ar*mre - cmi*mim + cor*ore - bi*oim
    // im_new = ar*mim + cmi*mre + cor*oim + bi*ore
    auto site = [&](ull mre, ull mim, ull ore, ull oim, bool cls, ull& nre, ull& nim) {
        ull cip = cls ? cmiP1 : cmiP0;   // +cmi
        ull cin = cls ? cmiP0 : cmiP1;   // -cmi
        ull cop = cls ? corP1 : corP0;   // +cor
        nre = fma2(arP, mre, fma2(cin, mim, fma2(cop, ore, mul2(nbiP, oim))));
        nim = fma2(arP, mim, fma2(cip, mre, fma2(cop, oim, mul2(biP, ore))));
    };

#pragma unroll
    for (int p = 0; p < 16; p++) {
        const int q = p ^ (int)VL15;
        if (VL15 != 0 && q < p) continue;        // one visit per pair-group
        const bool clsP = (__popc((unsigned)p & SL15) & 1) != 0;
        const bool clsQ = (__popc((unsigned)q & SL15) & 1) != 0;
        if (VLANE == 0) {
            if (VL15 == 0) {                      // partner = own pair, halves swapped
                ull ore = swp(reP[p]), oim = swp(imP[p]);
                ull nre, nim;
                site(reP[p], imP[p], ore, oim, clsP, nre, nim);
                reP[p] = nre; imP[p] = nim;
            } else {                              // local pair-group (p, q)
                ull oreP = V4 ? swp(reP[q]) : reP[q];
                ull oimP = V4 ? swp(imP[q]) : imP[q];
                ull oreQ = V4 ? swp(reP[p]) : reP[p];
                ull oimQ = V4 ? swp(imP[p]) : imP[p];
                ull nre1, nim1, nre2, nim2;
                site(reP[p], imP[p], oreP, oimP, clsP, nre1, nim1);
                site(reP[q], imP[q], oreQ, oimQ, clsQ, nre2, nim2);
                reP[p] = nre1; imP[p] = nim1;
                reP[q] = nre2; imP[q] = nim2;
            }
        } else {
            float a0, a1, b0, b1;
            upk(reP[q], a0, a1); upk(imP[q], b0, b1);
            float sa0 = __shfl_xor_sync(0xffffffffu, V4 ? a1 : a0, VLANE);
            float sa1 = __shfl_xor_sync(0xffffffffu, V4 ? a0 : a1, VLANE);
            float sb0 = __shfl_xor_sync(0xffffffffu, V4 ? b1 : b0, VLANE);
            float sb1 = __shfl_xor_sync(0xffffffffu, V4 ? b0 : b1, VLANE);
            ull oreP = pk(sa0, sa1), oimP = pk(sb0, sb1);
            if (VL15 == 0) {
                ull nre, nim;
                site(reP[p], imP[p], oreP, oimP, clsP, nre, nim);
                reP[p] = nre; imP[p] = nim;
            } else {                              // cross-lane pair-group (p, q)
                float c0, c1, d0, d1;
                upk(reP[p], c0, c1); upk(imP[p], d0, d1);
                float ta0 = __shfl_xor_sync(0xffffffffu, V4 ? c1 : c0, VLANE);
                float ta1 = __shfl_xor_sync(0xffffffffu, V4 ? c0 : c1, VLANE);
                float tb0 = __shfl_xor_sync(0xffffffffu, V4 ? d1 : d0, VLANE);
                float tb1 = __shfl_xor_sync(0xffffffffu, V4 ? d0 : d1, VLANE);
                ull oreQ = pk(ta0, ta1), oimQ = pk(tb0, tb1);
                ull nre1, nim1, nre2, nim2;
                site(reP[p], imP[p], oreP, oimP, clsP, nre1, nim1);
                site(reP[q], imP[q], oreQ, oimQ, clsQ, nre2, nim2);
                reP[p] = nre1; imP[p] = nim1;
                reP[q] = nre2; imP[q] = nim2;
            }
        }
    }
}

template<unsigned ZR>
__device__ __forceinline__ float zsum(const float* pr_, unsigned lane) {
    float s = 0.f;
#pragma unroll
    for (int r = 0; r < 32; r++) {
        if (__popc(r & (int)(ZR & 31u)) & 1) s -= pr_[r]; else s += pr_[r];
    }
    unsigned zs = ((unsigned)(__popc(lane & (ZR >> 5)) & 1)) << 31;
    return __uint_as_float(__float_as_uint(s) ^ zs);
}

__global__ __launch_bounds__(256)
void qnet_kernel(const float* __restrict__ x,
                 const float* __restrict__ Wp,
                 const float* __restrict__ bp,
                 const float* __restrict__ Wo,
                 const float* __restrict__ bo,
                 float* __restrict__ out,
                 int batch) {
    __shared__ float sg[NGATES * 4];
    for (int i = threadIdx.x; i < NGATES * 4; i += blockDim.x) sg[i] = g_gates[i];
    __syncthreads();

    const int warp = (int)((blockIdx.x * blockDim.x + threadIdx.x) >> 5);
    const unsigned lane = threadIdx.x & 31u;
    if (warp >= batch) return;

    // ---------------- projection: h = tanh(x @ Wp^T + bp) ------------------
    const float4* x4 = (const float4*)(x + (size_t)warp * DIM);
    const float4* w4 = (const float4*)Wp;
    float acc[NQ];
#pragma unroll
    for (int q = 0; q < NQ; q++) acc[q] = 0.f;
    for (int i = (int)lane; i < DIM4; i += 32) {
        float4 xv = x4[i];
#pragma unroll
        for (int q = 0; q < NQ; q++) {
            float4 wv = w4[q * DIM4 + i];
            acc[q] = fmaf(xv.x, wv.x, acc[q]);
            acc[q] = fmaf(xv.y, wv.y, acc[q]);
            acc[q] = fmaf(xv.z, wv.z, acc[q]);
            acc[q] = fmaf(xv.w, wv.w, acc[q]);
        }
    }
#pragma unroll
    for (int m = 16; m >= 1; m >>= 1)
#pragma unroll
        for (int q = 0; q < NQ; q++)
            acc[q] += __shfl_xor_sync(0xffffffffu, acc[q], m);

    float cq[NQ], sq[NQ];
#pragma unroll
    for (int q = 0; q < NQ; q++) {
        float a = acc[q] + bp[q];
        float e = __expf(2.0f * a);                       // tanh = 1 - 2/(e^{2a}+1)
        float h = 1.0f - __fdividef(2.0f, e + 1.0f);
        __sincosf(0.5f * h, &sq[q], &cq[q]);
    }

    // ---------------- embedding: real product state (packed) ----------------
    float lpv = 1.f;
#pragma unroll
    for (int k = 0; k < 5; k++)
        lpv *= ((lane >> k) & 1u) ? sq[5 + k] : cq[5 + k];

    ull reP[16], imP[16];
#pragma unroll
    for (int p = 0; p < 16; p++) {
        float v = lpv;
#pragma unroll
        for (int k = 0; k < 4; k++)
            v *= ((p >> k) & 1) ? sq[k] : cq[k];
        reP[p] = pk(v * cq[4], v * sq[4]);
        imP[p] = 0ull;
    }

    // ---------------- 4 entangling layers, CNOTs folded into masks ----------
#define G(l, q, V, S) gate<V, S>(reP, imP, sg + ((l) * NQ + (q)) * 4, lane)
    G(0,0,0x001,0x001); G(0,1,0x002,0x002); G(0,2,0x004,0x004); G(0,3,0x008,0x008); G(0,4,0x010,0x010);
    G(0,5,0x020,0x020); G(0,6,0x040,0x040); G(0,7,0x080,0x080); G(0,8,0x100,0x100); G(0,9,0x200,0x200);
    G(1,0,0x003,0x3FE); G(1,1,0x006,0x003); G(1,2,0x00C,0x007); G(1,3,0x018,0x00F); G(1,4,0x030,0x01F);
    G(1,5,0x060,0x03F); G(1,6,0x0C0,0x07F); G(1,7,0x180,0x0FF); G(1,8,0x300,0x1FF); G(1,9,0x203,0x3FF);
    G(2,0,0x005,0x2AB); G(2,1,0x00A,0x3FD); G(2,2,0x014,0x3FA); G(2,3,0x028,0x3F5); G(2,4,0x050,0x3EA);
    G(2,5,0x0A0,0x3D5); G(2,6,0x140,0x3AA); G(2,7,0x280,0x355); G(2,8,0x103,0x2AA); G(2,9,0x206,0x155);
    G(3,0,0x00F,0x0CD); G(3,1,0x01E,0x156); G(3,2,0x03C,0x2AC); G(3,3,0x078,0x159); G(3,4,0x0F0,0x2B3);
    G(3,5,0x1E0,0x166); G(3,6,0x3C0,0x2CC); G(3,7,0x383,0x199); G(3,8,0x305,0x333); G(3,9,0x209,0x266);
#undef G

    // ---------------- probabilities + Z expectations (remapped rows) --------
    float pr_[32];
#pragma unroll
    for (int p = 0; p < 16; p++) {
        ull pw = fma2(reP[p], reP[p], mul2(imP[p], imP[p]));
        upk(pw, pr_[p], pr_[p + 16]);
    }

    float z[NQ];
    z[0] = zsum<0x376>(pr_, lane); z[1] = zsum<0x19B>(pr_, lane);
    z[2] = zsum<0x337>(pr_, lane); z[3] = zsum<0x26E>(pr_, lane);
    z[4] = zsum<0x0DD>(pr_, lane); z[5] = zsum<0x1BB>(pr_, lane);
    z[6] = zsum<0x377>(pr_, lane); z[7] = zsum<0x2EE>(pr_, lane);
    z[8] = zsum<0x1DD>(pr_, lane); z[9] = zsum<0x3BB>(pr_, lane);

#pragma unroll
    for (int m = 16; m >= 1; m >>= 1)
#pragma unroll
        for (int q = 0; q < NQ; q++)
            z[q] += __shfl_xor_sync(0xffffffffu, z[q], m);

    // ---------------- output projection --------------------------------------
    if (lane < NOUT) {
        float o = bo[lane];
#pragma unroll
        for (int q = 0; q < NQ; q++)
            o = fmaf(z[q], Wo[lane * NQ + q], o);
        out[(size_t)warp * NOUT + lane] = o;
    }
}

extern "C" void kernel_launch(void* const* d_in, const int* in_sizes, int n_in,
                              void* d_out, int out_size) {
    const float* x  = (const float*)d_in[0];   // (B, 784)
    const float* Wp = (const float*)d_in[1];   // (10, 784)
    const float* bp = (const float*)d_in[2];   // (10,)
    const float* qw = (const float*)d_in[3];   // (4, 10, 3)
    const float* Wo = (const float*)d_in[4];   // (10, 10)
    const float* bo = (const float*)d_in[5];   // (10,)
    float* out = (float*)d_out;                // (B, 10)

    const int batch = in_sizes[0] / DIM;

    precompute_gates_kernel<<<1, 64>>>(qw);

    const int warps_per_block = 8;             // 256 threads
    const int blocks = (batch + warps_per_block - 1) / warps_per_block;
    qnet_kernel<<<blocks, warps_per_block * 32>>>(x, Wp, bp, Wo, bo, out, batch);
}

// round 6
// speedup vs baseline: 1.9809x; 1.1500x over previous
#include <cuda_runtime.h>

typedef unsigned long long ull;

#define NQ 10
#define LAYERS 4
#define DIM 784
#define DIM4 (DIM / 4)
#define NOUT 10
#define NGATES (LAYERS * NQ)

// Precomputed gate coefficients: for each (layer, qubit): {ar, ai, br, bi}
// Rot = [[a, b], [-conj(b), conj(a)]],
//   a = exp(-i(phi+omega)/2) cos(th/2),  b = -exp(+i(phi-omega)/2) sin(th/2)
__device__ float g_gates[NGATES * 4];

__global__ void precompute_gates_kernel(const float* __restrict__ qw) {
    int i = threadIdx.x;
    if (i < NGATES) {
        float phi = qw[i * 3 + 0], th = qw[i * 3 + 1], om = qw[i * 3 + 2];
        float s = sinf(th * 0.5f), c = cosf(th * 0.5f);
        float sp, cp, sm, cm;
        sincosf((phi + om) * 0.5f, &sp, &cp);
        sincosf((phi - om) * 0.5f, &sm, &cm);
        g_gates[i * 4 + 0] =  cp * c;
        g_gates[i * 4 + 1] = -sp * c;
        g_gates[i * 4 + 2] = -cm * s;
        g_gates[i * 4 + 3] = -sm * s;
    }
}

// ---------------- f32x2 helpers (FFMA2 only reachable via PTX) --------------
__device__ __forceinline__ ull pk(float a, float b) {
    ull r; asm("mov.b64 %0,{%1,%2};" : "=l"(r) : "f"(a), "f"(b)); return r;
}
__device__ __forceinline__ void upk(ull v, float& a, float& b) {
    asm("mov.b64 {%0,%1},%2;" : "=f"(a), "=f"(b) : "l"(v));
}
__device__ __forceinline__ ull swp(ull v) { float a, b; upk(v, a, b); return pk(b, a); }
__device__ __forceinline__ ull fma2(ull a, ull b, ull c) {
    ull d; asm("fma.rn.f32x2 %0,%1,%2,%3;" : "=l"(d) : "l"(a), "l"(b), "l"(c)); return d;
}
__device__ __forceinline__ ull mul2(ull a, ull b) {
    ull d; asm("mul.rn.f32x2 %0,%1,%2;" : "=l"(d) : "l"(a), "l"(b)); return d;
}

// complex multiply: (cr,ci) = (ar,ai)*(br,bi)
__device__ __forceinline__ void cmul(float ar, float ai, float br, float bi,
                                     float& cr, float& ci) {
    cr = fmaf(ar, br, -ai * bi);
    ci = fmaf(ar, bi,  ai * br);
}

// ---------------- generalized Rot gate --------------------------------------
// Physical index: bits[3:0]+bit4 = local (pair idx p = bits[3:0], half = bit4),
// bits[9:5] = lane. Gate pairs sites along phys XOR mask V; logical-bit-q value
// at a site is parity(S & phys).
template<unsigned V, unsigned S>
__device__ __forceinline__ void gate(ull* reP, ull* imP, const float* g, unsigned lane) {
    const float ar = g[0], ai = g[1], br = g[2], bi = g[3];
    constexpr unsigned VLANE = V >> 5;
    constexpr unsigned VL15  = V & 15u;
    constexpr bool     V4    = ((V >> 4) & 1u) != 0;
    constexpr unsigned SLANE = S >> 5;
    constexpr unsigned SL15  = S & 15u;
    constexpr bool     S4    = ((S >> 4) & 1u) != 0;

    unsigned sgn = SLANE ? ((unsigned)(__popc(lane & SLANE) & 1) << 31) : 0u;
    float cmi0  = __uint_as_float(__float_as_uint(ai) ^ sgn);
    float cor0  = __uint_as_float(__float_as_uint(br) ^ sgn);
    float cmi0h = S4 ? -cmi0 : cmi0;
    float cor0h = S4 ? -cor0 : cor0;
    ull arP   = pk(ar, ar);
    ull biP   = pk(bi, bi);
    ull nbiP  = pk(-bi, -bi);
    ull cmiP0 = pk(cmi0, cmi0h), cmiP1 = pk(-cmi0, -cmi0h);
    ull corP0 = pk(cor0, cor0h), corP1 = pk(-cor0, -cor0h);

    auto site = [&](ull mre, ull mim, ull ore, ull oim, bool cls, ull& nre, ull& nim) {
        ull cip = cls ? cmiP1 : cmiP0;
        ull cin = cls ? cmiP0 : cmiP1;
        ull cop = cls ? corP1 : corP0;
        nre = fma2(arP, mre, fma2(cin, mim, fma2(cop, ore, mul2(nbiP, oim))));
        nim = fma2(arP, mim, fma2(cip, mre, fma2(cop, oim, mul2(biP, ore))));
    };

#pragma unroll
    for (int p = 0; p < 16; p++) {
        const int q = p ^ (int)VL15;
        if (VL15 != 0 && q < p) continue;
        const bool clsP = (__popc((unsigned)p & SL15) & 1) != 0;
        const bool clsQ = (__popc((unsigned)q & SL15) & 1) != 0;
        if (VLANE == 0) {
            if (VL15 == 0) {
                ull ore = swp(reP[p]), oim = swp(imP[p]);
                ull nre, nim;
                site(reP[p], imP[p], ore, oim, clsP, nre, nim);
                reP[p] = nre; imP[p] = nim;
            } else {
                ull oreP = V4 ? swp(reP[q]) : reP[q];
                ull oimP = V4 ? swp(imP[q]) : imP[q];
                ull oreQ = V4 ? swp(reP[p]) : reP[p];
                ull oimQ = V4 ? swp(imP[p]) : imP[p];
                ull nre1, nim1, nre2, nim2;
                site(reP[p], imP[p], oreP, oimP, clsP, nre1, nim1);
                site(reP[q], imP[q], oreQ, oimQ, clsQ, nre2, nim2);
                reP[p] = nre1; imP[p] = nim1;
                reP[q] = nre2; imP[q] = nim2;
            }
        } else {
            float a0, a1, b0, b1;
            upk(reP[q], a0, a1); upk(imP[q], b0, b1);
            float sa0 = __shfl_xor_sync(0xffffffffu, V4 ? a1 : a0, VLANE);
            float sa1 = __shfl_xor_sync(0xffffffffu, V4 ? a0 : a1, VLANE);
            float sb0 = __shfl_xor_sync(0xffffffffu, V4 ? b1 : b0, VLANE);
            float sb1 = __shfl_xor_sync(0xffffffffu, V4 ? b0 : b1, VLANE);
            ull oreP = pk(sa0, sa1), oimP = pk(sb0, sb1);
            if (VL15 == 0) {
                ull nre, nim;
                site(reP[p], imP[p], oreP, oimP, clsP, nre, nim);
                reP[p] = nre; imP[p] = nim;
            } else {
                float c0, c1, d0, d1;
                upk(reP[p], c0, c1); upk(imP[p], d0, d1);
                float ta0 = __shfl_xor_sync(0xffffffffu, V4 ? c1 : c0, VLANE);
                float ta1 = __shfl_xor_sync(0xffffffffu, V4 ? c0 : c1, VLANE);
                float tb0 = __shfl_xor_sync(0xffffffffu, V4 ? d1 : d0, VLANE);
                float tb1 = __shfl_xor_sync(0xffffffffu, V4 ? d0 : d1, VLANE);
                ull oreQ = pk(ta0, ta1), oimQ = pk(tb0, tb1);
                ull nre1, nim1, nre2, nim2;
                site(reP[p], imP[p], oreP, oimP, clsP, nre1, nim1);
                site(reP[q], imP[q], oreQ, oimQ, clsQ, nre2, nim2);
                reP[p] = nre1; imP[p] = nim1;
                reP[q] = nre2; imP[q] = nim2;
            }
        }
    }
}

// sign-pack for packed Z accumulation: low half = site p (bit4=0), high = p|16
__device__ __forceinline__ ull zsgn(unsigned zr, int p) {
    unsigned lo = __popc((unsigned)p & (zr & 15u)) & 1u;
    unsigned hi = __popc(((unsigned)p | 16u) & (zr & 31u)) & 1u;
    return (ull)(lo ? 0xBF800000u : 0x3F800000u) |
           ((ull)(hi ? 0xBF800000u : 0x3F800000u) << 32);
}

__global__ __launch_bounds__(256)
void qnet_kernel(const float* __restrict__ x,
                 const float* __restrict__ Wp,
                 const float* __restrict__ bp,
                 const float* __restrict__ Wo,
                 const float* __restrict__ bo,
                 float* __restrict__ out,
                 int batch) {
    __shared__ float sg[NGATES * 4];
    for (int i = threadIdx.x; i < NGATES * 4; i += blockDim.x) sg[i] = g_gates[i];
    __syncthreads();

    const int warp = (int)((blockIdx.x * blockDim.x + threadIdx.x) >> 5);
    const unsigned lane = threadIdx.x & 31u;
    if (warp >= batch) return;

    // ---------------- projection: h = tanh(x @ Wp^T + bp) ------------------
    const float4* x4 = (const float4*)(x + (size_t)warp * DIM);
    const float4* w4 = (const float4*)Wp;
    float acc[NQ];
#pragma unroll
    for (int q = 0; q < NQ; q++) acc[q] = 0.f;
    for (int i = (int)lane; i < DIM4; i += 32) {
        float4 xv = x4[i];
#pragma unroll
        for (int q = 0; q < NQ; q++) {
            float4 wv = w4[q * DIM4 + i];
            acc[q] = fmaf(xv.x, wv.x, acc[q]);
            acc[q] = fmaf(xv.y, wv.y, acc[q]);
            acc[q] = fmaf(xv.z, wv.z, acc[q]);
            acc[q] = fmaf(xv.w, wv.w, acc[q]);
        }
    }
#pragma unroll
    for (int m = 16; m >= 1; m >>= 1)
#pragma unroll
        for (int q = 0; q < NQ; q++)
            acc[q] += __shfl_xor_sync(0xffffffffu, acc[q], m);

    // ---------------- per-qubit states (RY embedding folded with layer-0 Rot)
    // qubit state = Rot_q(layer0) * [cos(h/2), sin(h/2)]^T = (alpha_q, beta_q)
    float alr[NQ], ali[NQ], ber[NQ], bei[NQ];
#pragma unroll
    for (int q = 0; q < NQ; q++) {
        float a = acc[q] + bp[q];
        float e = __expf(2.0f * a);                       // tanh = 1 - 2/(e^{2a}+1)
        float h = 1.0f - __fdividef(2.0f, e + 1.0f);
        float s, c;
        __sincosf(0.5f * h, &s, &c);
        const float ar = sg[q * 4 + 0], ai = sg[q * 4 + 1];
        const float br = sg[q * 4 + 2], bi = sg[q * 4 + 3];
        // alpha = u00*c + u01*s ; beta = u10*c + u11*s
        // u00=(ar,ai) u01=(br,bi) u10=(-br,bi) u11=(ar,-ai)
        alr[q] = fmaf(ar, c,  br * s);
        ali[q] = fmaf(ai, c,  bi * s);
        ber[q] = fmaf(ar, s, -br * c);
        bei[q] = fmaf(bi, c, -ai * s);
    }

    // ---------------- product-state construction (prefix products) ----------
    // lane factor over qubits 5..9
    float Lr = ((lane >> 0) & 1u) ? ber[5] : alr[5];
    float Li = ((lane >> 0) & 1u) ? bei[5] : ali[5];
#pragma unroll
    for (int k = 1; k < 5; k++) {
        float fr = ((lane >> k) & 1u) ? ber[5 + k] : alr[5 + k];
        float fi = ((lane >> k) & 1u) ? bei[5 + k] : ali[5 + k];
        float nr, ni; cmul(Lr, Li, fr, fi, nr, ni);
        Lr = nr; Li = ni;
    }
    // t01[j] over qubits 0,1 ; t23[j] over qubits 2,3
    float t01r[4], t01i[4], ur[4], ui[4], vr[4], vi[4];
#pragma unroll
    for (int j = 0; j < 4; j++) {
        float f0r = (j & 1) ? ber[0] : alr[0], f0i = (j & 1) ? bei[0] : ali[0];
        float f1r = (j & 2) ? ber[1] : alr[1], f1i = (j & 2) ? bei[1] : ali[1];
        cmul(f0r, f0i, f1r, f1i, t01r[j], t01i[j]);
    }
    float LAr, LAi, LBr, LBi;
    cmul(Lr, Li, alr[4], ali[4], LAr, LAi);   // L * alpha4 (half 0)
    cmul(Lr, Li, ber[4], bei[4], LBr, LBi);   // L * beta4  (half 1)
#pragma unroll
    for (int j = 0; j < 4; j++) {
        float f2r = (j & 1) ? ber[2] : alr[2], f2i = (j & 1) ? bei[2] : ali[2];
        float f3r = (j & 2) ? ber[3] : alr[3], f3i = (j & 2) ? bei[3] : ali[3];
        float tr, ti; cmul(f2r, f2i, f3r, f3i, tr, ti);
        cmul(tr, ti, LAr, LAi, ur[j], ui[j]);
        cmul(tr, ti, LBr, LBi, vr[j], vi[j]);
    }
    ull reP[16], imP[16];
#pragma unroll
    for (int p = 0; p < 16; p++) {
        const int j = p & 3, j2 = p >> 2;
        float lr, li, hr, hi;
        cmul(t01r[j], t01i[j], ur[j2], ui[j2], lr, li);
        cmul(t01r[j], t01i[j], vr[j2], vi[j2], hr, hi);
        reP[p] = pk(lr, hr);
        imP[p] = pk(li, hi);
    }

    // ---------------- layers 1..3 (layer-0 folded above; CNOTs in masks) ----
#define G(l, q, V, S) gate<V, S>(reP, imP, sg + ((l) * NQ + (q)) * 4, lane)
    G(1,0,0x003,0x3FE); G(1,1,0x006,0x003); G(1,2,0x00C,0x007); G(1,3,0x018,0x00F); G(1,4,0x030,0x01F);
    G(1,5,0x060,0x03F); G(1,6,0x0C0,0x07F); G(1,7,0x180,0x0FF); G(1,8,0x300,0x1FF); G(1,9,0x203,0x3FF);
    G(2,0,0x005,0x2AB); G(2,1,0x00A,0x3FD); G(2,2,0x014,0x3FA); G(2,3,0x028,0x3F5); G(2,4,0x050,0x3EA);
    G(2,5,0x0A0,0x3D5); G(2,6,0x140,0x3AA); G(2,7,0x280,0x355); G(2,8,0x103,0x2AA); G(2,9,0x206,0x155);
    G(3,0,0x00F,0x0CD); G(3,1,0x01E,0x156); G(3,2,0x03C,0x2AC); G(3,3,0x078,0x159); G(3,4,0x0F0,0x2B3);
    G(3,5,0x1E0,0x166); G(3,6,0x3C0,0x2CC); G(3,7,0x383,0x199); G(3,8,0x305,0x333); G(3,9,0x209,0x266);
#undef G

    // ---------------- packed Z accumulation (remapped rows) ------------------
    constexpr unsigned ZRS[NQ] = {0x376, 0x19B, 0x337, 0x26E, 0x0DD,
                                  0x1BB, 0x377, 0x2EE, 0x1DD, 0x3BB};
    ull zP[NQ];
#pragma unroll
    for (int q = 0; q < NQ; q++) zP[q] = 0ull;
#pragma unroll
    for (int p = 0; p < 16; p++) {
        ull pw = fma2(reP[p], reP[p], mul2(imP[p], imP[p]));
#pragma unroll
        for (int q = 0; q < NQ; q++)
            zP[q] = fma2(zsgn(ZRS[q], p), pw, zP[q]);
    }
    float z[NQ];
#pragma unroll
    for (int q = 0; q < NQ; q++) {
        float lo, hi;
        upk(zP[q], lo, hi);
        float s = lo + hi;
        unsigned zs = ((unsigned)(__popc(lane & (ZRS[q] >> 5)) & 1)) << 31;
        z[q] = __uint_as_float(__float_as_uint(s) ^ zs);
    }
#pragma unroll
    for (int m = 16; m >= 1; m >>= 1)
#pragma unroll
        for (int q = 0; q < NQ; q++)
            z[q] += __shfl_xor_sync(0xffffffffu, z[q], m);

    // ---------------- output projection --------------------------------------
    if (lane < NOUT) {
        float o = bo[lane];
#pragma unroll
        for (int q = 0; q < NQ; q++)
            o = fmaf(z[q], Wo[lane * NQ + q], o);
        out[(size_t)warp * NOUT + lane] = o;
    }
}

extern "C" void kernel_launch(void* const* d_in, const int* in_sizes, int n_in,
                              void* d_out, int out_size) {
    const float* x  = (const float*)d_in[0];   // (B, 784)
    const float* Wp = (const float*)d_in[1];   // (10, 784)
    const float* bp = (const float*)d_in[2];   // (10,)
    const float* qw = (const float*)d_in[3];   // (4, 10, 3)
    const float* Wo = (const float*)d_in[4];   // (10, 10)
    const float* bo = (const float*)d_in[5];   // (10,)
    float* out = (float*)d_out;                // (B, 10)

    const int batch = in_sizes[0] / DIM;

    precompute_gates_kernel<<<1, 64>>>(qw);

    const int warps_per_block = 8;             // 256 threads
    const int blocks = (batch + warps_per_block - 1) / warps_per_block;
    qnet_kernel<<<blocks, warps_per_block * 32>>>(x, Wp, bp, Wo, bo, out, batch);
}